// round 3
// baseline (speedup 1.0000x reference)
#include <cuda_runtime.h>

#define BB 32
#define C 64
#define H 128
#define W 128
#define OUTC 64
#define KS 3
#define HIDDEN 128
#define WPB (OUTC*C*KS*KS)   // 36864 weights per sample

typedef unsigned long long ull;

// scratch (no allocations allowed)
__device__ float g_stats[BB*C];
__device__ float g_hidden[BB*HIDDEN];
__device__ float g_weight[(size_t)BB*WPB];

// ---------------- packed f32x2 helpers ----------------
__device__ __forceinline__ void ffma2(ull &d, ull a, ull b) {
    asm("fma.rn.f32x2 %0, %1, %2, %0;" : "+l"(d) : "l"(a), "l"(b));
}
__device__ __forceinline__ ull pack2(float lo, float hi) {
    ull r;
    asm("mov.b64 %0, {%1, %2};" : "=l"(r) : "f"(lo), "f"(hi));
    return r;
}
__device__ __forceinline__ void unpack2(float &lo, float &hi, ull v) {
    asm("mov.b64 {%0, %1}, %2;" : "=f"(lo), "=f"(hi) : "l"(v));
}

// ---------------- Kernel 1: per-(b,c) spatial mean ----------------
__global__ void stats_kernel(const float* __restrict__ x, float* __restrict__ stats) {
    int bc = blockIdx.x;                       // 0..B*C-1
    const float4* p = (const float4*)(x + (size_t)bc * (H*W));
    float s = 0.f;
    for (int i = threadIdx.x; i < (H*W)/4; i += 256) {
        float4 v = p[i];
        s += (v.x + v.y) + (v.z + v.w);
    }
    #pragma unroll
    for (int o = 16; o; o >>= 1) s += __shfl_down_sync(0xffffffffu, s, o);
    __shared__ float sm[8];
    if ((threadIdx.x & 31) == 0) sm[threadIdx.x >> 5] = s;
    __syncthreads();
    if (threadIdx.x < 8) {
        s = sm[threadIdx.x];
        #pragma unroll
        for (int o = 4; o; o >>= 1) s += __shfl_down_sync(0xffu, s, o);
        if (threadIdx.x == 0) stats[bc] = s * (1.0f / (H*W));
    }
}

// ---------------- Kernel 2: hidden = relu(stats @ W1 + b1) ----------------
__global__ void hidden_kernel(const float* __restrict__ stats,
                              const float* __restrict__ W1,
                              const float* __restrict__ b1,
                              float* __restrict__ hidden) {
    int b = blockIdx.x;
    int j = threadIdx.x;                       // 0..127
    __shared__ float s[C];
    if (j < C) s[j] = stats[b*C + j];
    __syncthreads();
    float acc = b1[j];
    #pragma unroll
    for (int c = 0; c < C; c++) acc = fmaf(s[c], W1[c*HIDDEN + j], acc);
    hidden[b*HIDDEN + j] = fmaxf(acc, 0.f);
}

// ---------------- Kernel 3: weight = hidden @ W2 + b2 ----------------
__global__ void weight_kernel(const float* __restrict__ hidden,
                              const float* __restrict__ W2,
                              const float* __restrict__ b2,
                              float* __restrict__ weight) {
    __shared__ float sh[BB*HIDDEN];            // 4096 floats = 16 KB
    for (int i = threadIdx.x; i < BB*HIDDEN; i += blockDim.x) sh[i] = hidden[i];
    __syncthreads();
    int j = blockIdx.x * blockDim.x + threadIdx.x;   // < 36864
    float bias = b2[j];
    float acc[BB];
    #pragma unroll
    for (int b = 0; b < BB; b++) acc[b] = bias;
    for (int k = 0; k < HIDDEN; k++) {
        float w = W2[(size_t)k * WPB + j];
        #pragma unroll
        for (int b = 0; b < BB; b++) acc[b] = fmaf(sh[b*HIDDEN + k], w, acc[b]);
    }
    #pragma unroll
    for (int b = 0; b < BB; b++) weight[(size_t)b * WPB + j] = acc[b];
}

// ---------------- Kernel 4: per-sample 3x3 conv via packed f32x2 ----------------
// Block: 1 batch x 16 out-channels x 16x16 spatial tile, 256 threads.
// Thread: 1 o-channel x 4x4 pixels, accumulated as 8 f32x2 pairs.
#define TO 16
#define TS 16
#define CCH 8
#define XP 20     // x smem pitch: EVEN -> 8B-aligned float2 loads
#define WP2 146   // weight smem per-o stride (duplicated pairs; 146 mod 32 = 18 -> conflict-free)

__global__ __launch_bounds__(256, 3)
void conv_kernel(const float* __restrict__ x,
                 float* __restrict__ out) {
    __shared__ float s_x[CCH*18*XP];   // 2880 floats = 11.5 KB
    __shared__ float s_w[TO*WP2];      // 2336 floats =  9.3 KB

    int tile = blockIdx.x;             // 0..63  (8x8 tiles of 16x16)
    int ty0 = (tile >> 3) * TS;
    int tx0 = (tile & 7) * TS;
    int og0 = blockIdx.y * TO;
    int b   = blockIdx.z;
    int tid = threadIdx.x;
    int o   = tid & 15;
    int pg  = tid >> 4;
    int sy  = (pg >> 2) << 2;
    int sx  = (pg & 3) << 2;

    const float* xb = x + (size_t)b * C * H * W;
    const float* wb = g_weight + (size_t)b * WPB;

    ull accA[4], accB[4];              // A = pixels (sx+0,sx+1), B = (sx+2,sx+3)
    #pragma unroll
    for (int i = 0; i < 4; i++) { accA[i] = 0ull; accB[i] = 0ull; }

    for (int cc = 0; cc < C; cc += CCH) {
        __syncthreads();
        // stage x tile [CCH][18][18] (halo, zero-padded at borders)
        for (int idx = tid; idx < CCH*18*18; idx += 256) {
            int c  = idx / (18*18);
            int r  = idx - c*(18*18);
            int yy = r / 18;
            int xx = r - yy*18;
            int gy = ty0 + yy - 1, gx = tx0 + xx - 1;
            float v = 0.f;
            if ((unsigned)gy < (unsigned)H && (unsigned)gx < (unsigned)W)
                v = xb[(size_t)(cc + c) * (H*W) + gy*W + gx];
            s_x[c*18*XP + yy*XP + xx] = v;
        }
        // stage weights duplicated: s_w[o*WP2 + c*18 + k*2 + {0,1}] = w
        for (int idx = tid; idx < TO*CCH*9; idx += 256) {
            int oo = idx / (CCH*9);
            int r  = idx - oo*(CCH*9);         // c*9 + k
            int c  = r / 9;
            int k  = r - c*9;
            float w = wb[(size_t)((og0 + oo)*C + cc + c)*9 + k];
            int base = oo*WP2 + c*18 + k*2;
            s_w[base]     = w;
            s_w[base + 1] = w;
        }
        __syncthreads();

        #pragma unroll
        for (int c = 0; c < CCH; c++) {
            // packed weights {w,w} for this (o, c): 9 LDS.64
            ull wq[9];
            const float* wrow = &s_w[o*WP2 + c*18];
            #pragma unroll
            for (int k = 0; k < 9; k++)
                wq[k] = *(const ull*)&wrow[k*2];

            const float* sxc = &s_x[c*18*XP + sy*XP + sx];
            #pragma unroll
            for (int r = 0; r < 6; r++) {
                const float2* row = (const float2*)&sxc[r*XP];
                float2 a0 = row[0], a1 = row[1], a2 = row[2];   // (v0,v1)(v2,v3)(v4,v5)
                ull A0 = pack2(a0.x, a0.y);
                ull A1 = pack2(a1.x, a1.y);
                ull A2 = pack2(a2.x, a2.y);
                ull M0 = pack2(a0.y, a1.x);                      // (v1,v2)
                ull M1 = pack2(a1.y, a2.x);                      // (v3,v4)
                #pragma unroll
                for (int py = 0; py < 4; py++) {
                    int kh = r - py;
                    if (kh < 0 || kh > 2) continue;              // compile-time pruned
                    ffma2(accA[py], A0, wq[kh*3 + 0]);
                    ffma2(accB[py], A1, wq[kh*3 + 0]);
                    ffma2(accA[py], M0, wq[kh*3 + 1]);
                    ffma2(accB[py], M1, wq[kh*3 + 1]);
                    ffma2(accA[py], A1, wq[kh*3 + 2]);
                    ffma2(accB[py], A2, wq[kh*3 + 2]);
                }
            }
        }
    }

    float* ob = out + ((size_t)(b*OUTC + og0 + o) * H + ty0 + sy) * W + tx0 + sx;
    #pragma unroll
    for (int py = 0; py < 4; py++) {
        float p0, p1, p2, p3;
        unpack2(p0, p1, accA[py]);
        unpack2(p2, p3, accB[py]);
        *(float4*)(ob + (size_t)py*W) = make_float4(p0, p1, p2, p3);
    }
}

extern "C" void kernel_launch(void* const* d_in, const int* in_sizes, int n_in,
                              void* d_out, int out_size) {
    const float* x  = (const float*)d_in[0];   // [32,64,128,128]
    const float* W1 = (const float*)d_in[1];   // [64,128]
    const float* b1 = (const float*)d_in[2];   // [128]
    const float* W2 = (const float*)d_in[3];   // [128,36864]
    const float* b2 = (const float*)d_in[4];   // [36864]
    float* out = (float*)d_out;                // [32,64,128,128]

    float* stats;  cudaGetSymbolAddress((void**)&stats,  g_stats);
    float* hidden; cudaGetSymbolAddress((void**)&hidden, g_hidden);
    float* weight; cudaGetSymbolAddress((void**)&weight, g_weight);

    stats_kernel<<<BB*C, 256>>>(x, stats);
    hidden_kernel<<<BB, HIDDEN>>>(stats, W1, b1, hidden);
    weight_kernel<<<WPB/128, 128>>>(hidden, W2, b2, weight);
    dim3 grid(64, OUTC/TO, BB);
    conv_kernel<<<grid, 256>>>(x, out);
}

// round 7
// speedup vs baseline: 1.3963x; 1.3963x over previous
#include <cuda_runtime.h>
#include <cuda_bf16.h>
#include <cstdint>

#define BB 32
#define C 64
#define H 128
#define W 128
#define HW (H*W)
#define OUTC 64
#define HIDDEN 128
#define WPB (OUTC*C*9)

typedef unsigned int u32;
typedef unsigned long long u64;

// -------- global scratch (no allocations allowed) --------
__device__ float g_stats[BB*C];
__device__ float g_hidden[BB*HIDDEN];
__device__ float g_weight[(size_t)BB*WPB];                 // fp32 weights (fixup)
__device__ __nv_bfloat16 g_wh[(size_t)BB*9*OUTC*C];        // [b][tap][o][c]
__device__ __nv_bfloat16 g_wl[(size_t)BB*9*OUTC*C];
__device__ __nv_bfloat16 g_xh[(size_t)BB*HW*C];            // [b][pixel][c] transposed
__device__ __nv_bfloat16 g_xl[(size_t)BB*HW*C];

#define SWZ128(x) ((x) ^ (((x) >> 3) & 0x70))

// warp-level bf16 MMA, D/C fp32: D = A(16x16,row) * B(16x8,col) + D
__device__ __forceinline__ void mma16816(float* c, u32 a0, u32 a1, u32 a2, u32 a3,
                                         u32 b0, u32 b1) {
    asm("mma.sync.aligned.m16n8k16.row.col.f32.bf16.bf16.f32 "
        "{%0,%1,%2,%3}, {%4,%5,%6,%7}, {%8,%9}, {%0,%1,%2,%3};"
        : "+f"(c[0]), "+f"(c[1]), "+f"(c[2]), "+f"(c[3])
        : "r"(a0), "r"(a1), "r"(a2), "r"(a3), "r"(b0), "r"(b1));
}

// ---------------- Kernel 1: per-(b,c) spatial mean ----------------
__global__ void stats_kernel(const float* __restrict__ x, float* __restrict__ stats) {
    int bc = blockIdx.x;
    const float4* p = (const float4*)(x + (size_t)bc * HW);
    float s = 0.f;
    for (int i = threadIdx.x; i < HW/4; i += 256) {
        float4 v = p[i];
        s += (v.x + v.y) + (v.z + v.w);
    }
    #pragma unroll
    for (int o = 16; o; o >>= 1) s += __shfl_down_sync(0xffffffffu, s, o);
    __shared__ float sm[8];
    if ((threadIdx.x & 31) == 0) sm[threadIdx.x >> 5] = s;
    __syncthreads();
    if (threadIdx.x < 8) {
        s = sm[threadIdx.x];
        #pragma unroll
        for (int o = 4; o; o >>= 1) s += __shfl_down_sync(0xffu, s, o);
        if (threadIdx.x == 0) stats[bc] = s * (1.0f / HW);
    }
}

// ---------------- Kernel 2: hidden = relu(stats @ W1 + b1) ----------------
__global__ void hidden_kernel(const float* __restrict__ stats,
                              const float* __restrict__ W1,
                              const float* __restrict__ b1,
                              float* __restrict__ hidden) {
    int b = blockIdx.x, j = threadIdx.x;
    __shared__ float s[C];
    if (j < C) s[j] = stats[b*C + j];
    __syncthreads();
    float acc = b1[j];
    #pragma unroll
    for (int c = 0; c < C; c++) acc = fmaf(s[c], W1[c*HIDDEN + j], acc);
    hidden[b*HIDDEN + j] = fmaxf(acc, 0.f);
}

// ---------------- Kernel 3: weight = hidden @ W2 + b2, + bf16 hi/lo rearrange ----------------
__global__ void weight_kernel(const float* __restrict__ hidden,
                              const float* __restrict__ W2,
                              const float* __restrict__ b2,
                              float* __restrict__ weight,
                              __nv_bfloat16* __restrict__ wh,
                              __nv_bfloat16* __restrict__ wl) {
    __shared__ float sh[BB*HIDDEN];
    for (int i = threadIdx.x; i < BB*HIDDEN; i += blockDim.x) sh[i] = hidden[i];
    __syncthreads();
    int j = blockIdx.x * blockDim.x + threadIdx.x;     // < 36864
    float bias = b2[j];
    float acc[BB];
    #pragma unroll
    for (int b = 0; b < BB; b++) acc[b] = bias;
    for (int k = 0; k < HIDDEN; k++) {
        float w = W2[(size_t)k * WPB + j];
        #pragma unroll
        for (int b = 0; b < BB; b++) acc[b] = fmaf(sh[b*HIDDEN + k], w, acc[b]);
    }
    int o = j / 576, rem = j - o*576, c = rem / 9, tap = rem - c*9;
    #pragma unroll
    for (int b = 0; b < BB; b++) {
        float w = acc[b];
        weight[(size_t)b*WPB + j] = w;
        __nv_bfloat16 hh = __float2bfloat16(w);
        __nv_bfloat16 ll = __float2bfloat16(w - __bfloat162float(hh));
        size_t d = ((size_t)(b*9 + tap)*OUTC + o)*C + c;
        wh[d] = hh; wl[d] = ll;
    }
}

// ---------------- Kernel 4: transpose x -> [b][pixel][c] bf16 hi/lo ----------------
__global__ void transpose_kernel(const float* __restrict__ x,
                                 __nv_bfloat16* __restrict__ xh,
                                 __nv_bfloat16* __restrict__ xl) {
    __shared__ float s[C][129];
    int b = blockIdx.y, p0 = blockIdx.x * 128;
    const float4* x4 = (const float4*)(x + (size_t)b * C * HW);
    for (int idx = threadIdx.x; idx < C*32; idx += 256) {
        int c = idx >> 5, q = idx & 31;
        float4 v = x4[(size_t)c*(HW/4) + p0/4 + q];
        s[c][q*4+0] = v.x; s[c][q*4+1] = v.y; s[c][q*4+2] = v.z; s[c][q*4+3] = v.w;
    }
    __syncthreads();
    int wid = threadIdx.x >> 5, lane = threadIdx.x & 31;
    for (int pp = wid; pp < 128; pp += 8) {
        int c = lane * 2;
        float v0 = s[c][pp], v1 = s[c+1][pp];
        __nv_bfloat16 h0 = __float2bfloat16(v0);
        __nv_bfloat16 h1 = __float2bfloat16(v1);
        __nv_bfloat162 hp, lp;
        hp.x = h0; hp.y = h1;
        lp.x = __float2bfloat16(v0 - __bfloat162float(h0));
        lp.y = __float2bfloat16(v1 - __bfloat162float(h1));
        size_t off = ((size_t)b*HW + p0 + pp)*C + c;
        *(__nv_bfloat162*)(xh + off) = hp;
        *(__nv_bfloat162*)(xl + off) = lp;
    }
}

// ---------------- Kernel 5: shift-GEMM conv via mma.sync bf16 ----------------
// Block: 1 sample, 2 image rows (256 px), 32 out-ch. 8 warps, warp = 32px x 32oc.
// A window: flat pixels [p0-129, p0+384] = 514 rows of 128B (SW128), hi+lo.
// W: [split][tap][32 o-rows x 128B] (SW128).
#define AROWS 514
#define ASTRIDE 66560            // 65*1024 (>= 514*128, 1024-aligned stride)
#define WTILE 4096               // 32 o-rows * 128B per (split, tap)
#define CONV_SMEM (2*ASTRIDE + 18*WTILE + 1024)

extern __shared__ unsigned char g_dsm[];

__global__ __launch_bounds__(256, 1)
void conv_kernel(const __nv_bfloat16* __restrict__ xh, const __nv_bfloat16* __restrict__ xl,
                 const __nv_bfloat16* __restrict__ wh, const __nv_bfloat16* __restrict__ wl,
                 float* __restrict__ out) {
    uintptr_t dynp = (uintptr_t)g_dsm;
    unsigned char* smb = (unsigned char*)((dynp + 1023) & ~(uintptr_t)1023);
    unsigned char* sAh = smb;
    unsigned char* sAl = smb + ASTRIDE;
    unsigned char* sW  = smb + 2*ASTRIDE;

    int tid = threadIdx.x, wid = tid >> 5, lane = tid & 31;
    int g = lane >> 2, t4 = lane & 3;
    int yp = blockIdx.x, og = blockIdx.y, b = blockIdx.z;
    int p0 = yp * 256;

    // ---- stage weights: [split][tap][o 0..31][8 chunks], SW128 ----
    for (int idx = tid; idx < 2*9*32*8; idx += 256) {
        int s  = idx / (9*32*8);
        int r  = idx % (9*32*8);
        int t  = r / (32*8);
        int r2 = r % (32*8);
        int o  = r2 >> 3, ch = r2 & 7;
        const uint4* src = s ? (const uint4*)wl : (const uint4*)wh;
        uint4 v = src[((size_t)(b*9 + t)*OUTC + og*32 + o)*8 + ch];
        *(uint4*)(sW + (s*9 + t)*WTILE + SWZ128(o*128 + ch*16)) = v;
    }

    // ---- stage A window (hi+lo), zero-padded outside [0,HW) ----
    const uint4* xh4 = (const uint4*)xh;
    const uint4* xl4 = (const uint4*)xl;
    int basef = p0 - 129;
    for (int idx = tid; idx < AROWS*8; idx += 256) {
        int r = idx >> 3, ch = idx & 7;
        int p = basef + r;
        uint4 vh = make_uint4(0,0,0,0), vv = make_uint4(0,0,0,0);
        if ((unsigned)p < (unsigned)HW) {
            size_t o8 = ((size_t)b*HW + p)*8 + ch;
            vh = xh4[o8]; vv = xl4[o8];
        }
        u32 off = SWZ128(r*128 + ch*16);
        *(uint4*)(sAh + off) = vh;
        *(uint4*)(sAl + off) = vv;
    }
    __syncthreads();

    float acc[2][4][4];
    #pragma unroll
    for (int mt = 0; mt < 2; mt++)
        #pragma unroll
        for (int nt = 0; nt < 4; nt++)
            #pragma unroll
            for (int i = 0; i < 4; i++) acc[mt][nt][i] = 0.f;

    u32 xorw = (u32)(g * 16);   // B-read swizzle term (o&7 == g)

    #pragma unroll 1
    for (int sp = 0; sp < 3; sp++) {
        // splits: 0 = Ah*Wh, 1 = Ah*Wl, 2 = Al*Wh
        const unsigned char* Ab = (sp == 2) ? sAl : sAh;
        const unsigned char* Wb = sW + ((sp == 1) ? 9 : 0) * WTILE;
        #pragma unroll 1
        for (int tap = 0; tap < 9; tap++) {
            int dy = tap / 3, dx = tap - dy*3;
            int rb = wid*32 + dy*128 + dx + g;        // A row for m-frag base
            u32 xorv = (u32)(((dx + g) & 7) * 16);    // A-read swizzle term
            const unsigned char* Wt = Wb + tap * WTILE;
            const unsigned char* A0 = Ab + rb * 128;
            #pragma unroll
            for (int kt = 0; kt < 4; kt++) {
                u32 aoff = (u32)(kt*32 + 4*t4);
                u32 oA  = aoff ^ xorv;
                u32 oA2 = (aoff + 16) ^ xorv;
                u32 bo0 = aoff ^ xorw;
                u32 bo1 = (aoff + 16) ^ xorw;
                u32 bfr[4][2];
                #pragma unroll
                for (int nt = 0; nt < 4; nt++) {
                    const unsigned char* wrow = Wt + (nt*8 + g)*128;
                    bfr[nt][0] = *(const u32*)(wrow + bo0);
                    bfr[nt][1] = *(const u32*)(wrow + bo1);
                }
                #pragma unroll
                for (int mt = 0; mt < 2; mt++) {
                    const unsigned char* Am = A0 + mt*16*128;
                    u32 a0 = *(const u32*)(Am + oA);
                    u32 a1 = *(const u32*)(Am + 8*128 + oA);
                    u32 a2 = *(const u32*)(Am + oA2);
                    u32 a3 = *(const u32*)(Am + 8*128 + oA2);
                    #pragma unroll
                    for (int nt = 0; nt < 4; nt++)
                        mma16816(acc[mt][nt], a0, a1, a2, a3, bfr[nt][0], bfr[nt][1]);
                }
            }
        }
    }

    // ---- epilogue: D frag c0=(m=g,n=2t4) c1=(g,2t4+1) c2=(g+8,2t4) c3=(g+8,2t4+1) ----
    #pragma unroll
    for (int mt = 0; mt < 2; mt++) {
        int pl = wid*32 + mt*16 + g;
        #pragma unroll
        for (int nt = 0; nt < 4; nt++) {
            int o = og*32 + nt*8 + 2*t4;
            size_t d = ((size_t)(b*OUTC + o))*HW + p0 + pl;
            out[d]          = acc[mt][nt][0];
            out[d + HW]     = acc[mt][nt][1];
            out[d + 8]      = acc[mt][nt][2];
            out[d + HW + 8] = acc[mt][nt][3];
        }
    }
}

// ---------------- Kernel 6: subtract wrapped edge contributions ----------------
__global__ void fixup_kernel(const float* __restrict__ x, float* __restrict__ out) {
    extern __shared__ float fs[];
    float* w6 = fs;                    // 64o*64c*6
    float* Rs = fs + 64*64*6;          // 64c*131
    float* Ls = Rs + 64*131;           // 64c*130
    int b = blockIdx.x, tid = threadIdx.x;
    const float* wsrc = g_weight + (size_t)b*WPB;
    for (int idx = tid; idx < 64*64*6; idx += 256) {
        int o = idx/(64*6), r = idx%(64*6), c = r/6, j = r%6;
        int dy = j >> 1, side = j & 1;
        w6[idx] = wsrc[(o*64 + c)*9 + dy*3 + (side ? 2 : 0)];
    }
    const float* xb = x + (size_t)b * C * HW;
    for (int idx = tid; idx < 64*131; idx += 256) {
        int c = idx/131, jj = idx%131;
        int q = jj - 1;                 // value = Xflat(q*128 - 1)
        float v = 0.f;
        if (q >= 1 && q <= 128) v = xb[(size_t)c*HW + q*128 - 1];
        Rs[idx] = v;
    }
    for (int idx = tid; idx < 64*130; idx += 256) {
        int c = idx/130, u = idx%130;   // value = Xflat(u*128)
        float v = 0.f;
        if (u <= 127) v = xb[(size_t)c*HW + u*128];
        Ls[idx] = v;
    }
    __syncthreads();
    for (int t = tid; t < 64*128; t += 256) {
        int o = t >> 7, y = t & 127;
        float a0 = 0.f, a1 = 0.f;
        for (int c = 0; c < 64; c++) {
            const float* wp = &w6[(o*64 + c)*6];
            const float* rp = &Rs[c*131 + y];
            const float* lp = &Ls[c*130 + y];
            a0 += wp[0]*rp[0] + wp[2]*rp[1] + wp[4]*rp[2];
            a1 += wp[1]*lp[0] + wp[3]*lp[1] + wp[5]*lp[2];
        }
        size_t base = ((size_t)(b*OUTC + o))*HW + (size_t)y*128;
        out[base]       -= a0;
        out[base + 127] -= a1;
    }
}

extern "C" void kernel_launch(void* const* d_in, const int* in_sizes, int n_in,
                              void* d_out, int out_size) {
    const float* x  = (const float*)d_in[0];
    const float* W1 = (const float*)d_in[1];
    const float* b1 = (const float*)d_in[2];
    const float* W2 = (const float*)d_in[3];
    const float* b2 = (const float*)d_in[4];
    float* out = (float*)d_out;

    float *stats, *hidden, *weight;
    __nv_bfloat16 *wh, *wl, *xh, *xl;
    cudaGetSymbolAddress((void**)&stats,  g_stats);
    cudaGetSymbolAddress((void**)&hidden, g_hidden);
    cudaGetSymbolAddress((void**)&weight, g_weight);
    cudaGetSymbolAddress((void**)&wh, g_wh);
    cudaGetSymbolAddress((void**)&wl, g_wl);
    cudaGetSymbolAddress((void**)&xh, g_xh);
    cudaGetSymbolAddress((void**)&xl, g_xl);

    cudaFuncSetAttribute(conv_kernel,  cudaFuncAttributeMaxDynamicSharedMemorySize, CONV_SMEM);
    cudaFuncSetAttribute(fixup_kernel, cudaFuncAttributeMaxDynamicSharedMemorySize, (64*64*6 + 64*131 + 64*130) * 4);

    stats_kernel<<<BB*C, 256>>>(x, stats);
    hidden_kernel<<<BB, HIDDEN>>>(stats, W1, b1, hidden);
    weight_kernel<<<WPB/128, 128>>>(hidden, W2, b2, weight, wh, wl);
    dim3 tg(HW/128, BB);
    transpose_kernel<<<tg, 256>>>(x, xh, xl);
    dim3 cg(64, 2, BB);
    conv_kernel<<<cg, 256, CONV_SMEM>>>(xh, xl, wh, wl, out);
    fixup_kernel<<<BB, 256, (64*64*6 + 64*131 + 64*130) * 4>>>(x, out);
}

// round 8
// speedup vs baseline: 2.5723x; 1.8423x over previous
#include <cuda_runtime.h>
#include <cuda_bf16.h>
#include <cuda_fp16.h>
#include <cstdint>

#define BB 32
#define C 64
#define H 128
#define W 128
#define HW (H*W)
#define OUTC 64
#define HIDDEN 128
#define WPB (OUTC*C*9)

typedef unsigned int u32;
typedef unsigned long long u64;

// -------- global scratch (no allocations allowed) --------
__device__ float g_stats[BB*C];
__device__ float g_hidden[BB*HIDDEN];
__device__ float g_weight[(size_t)BB*WPB];          // fp32 weights (fixup)
__device__ __half g_wh[(size_t)BB*9*OUTC*C];        // [b][tap][o][c] fp16
__device__ __half g_xh[(size_t)BB*HW*C];            // [b][pixel][c] fp16 transposed

#define SWZ128(x) ((x) ^ (((x) >> 3) & 0x70))

// warp-level fp16 MMA, D/C fp32: D = A(16x16,row) * B(16x8,col) + D
__device__ __forceinline__ void mma16816(float* c, u32 a0, u32 a1, u32 a2, u32 a3,
                                         u32 b0, u32 b1) {
    asm("mma.sync.aligned.m16n8k16.row.col.f32.f16.f16.f32 "
        "{%0,%1,%2,%3}, {%4,%5,%6,%7}, {%8,%9}, {%0,%1,%2,%3};"
        : "+f"(c[0]), "+f"(c[1]), "+f"(c[2]), "+f"(c[3])
        : "r"(a0), "r"(a1), "r"(a2), "r"(a3), "r"(b0), "r"(b1));
}

// ---------------- Kernel 1: per-(b,c) spatial mean ----------------
__global__ void stats_kernel(const float* __restrict__ x, float* __restrict__ stats) {
    int bc = blockIdx.x;
    const float4* p = (const float4*)(x + (size_t)bc * HW);
    float s = 0.f;
    for (int i = threadIdx.x; i < HW/4; i += 256) {
        float4 v = p[i];
        s += (v.x + v.y) + (v.z + v.w);
    }
    #pragma unroll
    for (int o = 16; o; o >>= 1) s += __shfl_down_sync(0xffffffffu, s, o);
    __shared__ float sm[8];
    if ((threadIdx.x & 31) == 0) sm[threadIdx.x >> 5] = s;
    __syncthreads();
    if (threadIdx.x < 8) {
        s = sm[threadIdx.x];
        #pragma unroll
        for (int o = 4; o; o >>= 1) s += __shfl_down_sync(0xffu, s, o);
        if (threadIdx.x == 0) stats[bc] = s * (1.0f / HW);
    }
}

// ---------------- Kernel 2: hidden = relu(stats @ W1 + b1) ----------------
__global__ void hidden_kernel(const float* __restrict__ stats,
                              const float* __restrict__ W1,
                              const float* __restrict__ b1,
                              float* __restrict__ hidden) {
    int b = blockIdx.x, j = threadIdx.x;
    __shared__ float s[C];
    if (j < C) s[j] = stats[b*C + j];
    __syncthreads();
    float acc = b1[j];
    #pragma unroll
    for (int c = 0; c < C; c++) acc = fmaf(s[c], W1[c*HIDDEN + j], acc);
    hidden[b*HIDDEN + j] = fmaxf(acc, 0.f);
}

// ---------------- Kernel 3: weight = hidden @ W2 + b2, + fp16 rearrange ----------------
__global__ void weight_kernel(const float* __restrict__ hidden,
                              const float* __restrict__ W2,
                              const float* __restrict__ b2,
                              float* __restrict__ weight,
                              __half* __restrict__ wh) {
    __shared__ float sh[BB*HIDDEN];
    for (int i = threadIdx.x; i < BB*HIDDEN; i += blockDim.x) sh[i] = hidden[i];
    __syncthreads();
    int j = blockIdx.x * blockDim.x + threadIdx.x;     // < 36864
    float bias = b2[j];
    float acc[BB];
    #pragma unroll
    for (int b = 0; b < BB; b++) acc[b] = bias;
    for (int k = 0; k < HIDDEN; k++) {
        float w = W2[(size_t)k * WPB + j];
        #pragma unroll
        for (int b = 0; b < BB; b++) acc[b] = fmaf(sh[b*HIDDEN + k], w, acc[b]);
    }
    int o = j / 576, rem = j - o*576, c = rem / 9, tap = rem - c*9;
    #pragma unroll
    for (int b = 0; b < BB; b++) {
        float w = acc[b];
        weight[(size_t)b*WPB + j] = w;
        wh[((size_t)(b*9 + tap)*OUTC + o)*C + c] = __float2half(w);
    }
}

// ---------------- Kernel 4: transpose x -> [b][pixel][c] fp16 ----------------
__global__ void transpose_kernel(const float* __restrict__ x,
                                 __half* __restrict__ xh) {
    __shared__ float s[C][129];
    int b = blockIdx.y, p0 = blockIdx.x * 128;
    const float4* x4 = (const float4*)(x + (size_t)b * C * HW);
    for (int idx = threadIdx.x; idx < C*32; idx += 256) {
        int c = idx >> 5, q = idx & 31;
        float4 v = x4[(size_t)c*(HW/4) + p0/4 + q];
        s[c][q*4+0] = v.x; s[c][q*4+1] = v.y; s[c][q*4+2] = v.z; s[c][q*4+3] = v.w;
    }
    __syncthreads();
    int wid = threadIdx.x >> 5, lane = threadIdx.x & 31;
    for (int pp = wid; pp < 128; pp += 8) {
        int c = lane * 2;
        __half2 hp;
        hp.x = __float2half(s[c][pp]);
        hp.y = __float2half(s[c+1][pp]);
        *(__half2*)(xh + ((size_t)b*HW + p0 + pp)*C + c) = hp;
    }
}

// ---------------- Kernel 5: shift-GEMM conv via mma.sync fp16 ----------------
// Block: 1 sample, 2 image rows (256 px), 32 out-ch. 8 warps, warp = 32px x 32oc.
// A window: flat pixels [p0-129, p0+384] = 514 rows of 128B (SW128).
// W: [tap][32 o-rows x 128B] (SW128).
#define AROWS 514
#define ASTRIDE 66560            // 65*1024 (>= 514*128, 1024-aligned)
#define WTILE 4096               // 32 o-rows * 128B per tap
#define CONV_SMEM (ASTRIDE + 9*WTILE + 1024)

extern __shared__ unsigned char g_dsm[];

__global__ __launch_bounds__(256, 2)
void conv_kernel(const __half* __restrict__ xh,
                 const __half* __restrict__ wh,
                 float* __restrict__ out) {
    uintptr_t dynp = (uintptr_t)g_dsm;
    unsigned char* smb = (unsigned char*)((dynp + 1023) & ~(uintptr_t)1023);
    unsigned char* sA = smb;
    unsigned char* sW = smb + ASTRIDE;

    int tid = threadIdx.x, wid = tid >> 5, lane = tid & 31;
    int g = lane >> 2, t4 = lane & 3;
    int yp = blockIdx.x, og = blockIdx.y, b = blockIdx.z;
    int p0 = yp * 256;

    // ---- stage weights: [tap][o 0..31][8 chunks], SW128 ----
    for (int idx = tid; idx < 9*32*8; idx += 256) {
        int t  = idx / (32*8);
        int r2 = idx % (32*8);
        int o  = r2 >> 3, ch = r2 & 7;
        uint4 v = ((const uint4*)wh)[((size_t)(b*9 + t)*OUTC + og*32 + o)*8 + ch];
        *(uint4*)(sW + t*WTILE + SWZ128(o*128 + ch*16)) = v;
    }

    // ---- stage A window, zero-padded outside [0,HW) ----
    const uint4* xh4 = (const uint4*)xh;
    int basef = p0 - 129;
    for (int idx = tid; idx < AROWS*8; idx += 256) {
        int r = idx >> 3, ch = idx & 7;
        int p = basef + r;
        uint4 vh = make_uint4(0,0,0,0);
        if ((unsigned)p < (unsigned)HW)
            vh = xh4[((size_t)b*HW + p)*8 + ch];
        *(uint4*)(sA + SWZ128(r*128 + ch*16)) = vh;
    }
    __syncthreads();

    float acc[2][4][4];
    #pragma unroll
    for (int mt = 0; mt < 2; mt++)
        #pragma unroll
        for (int nt = 0; nt < 4; nt++)
            #pragma unroll
            for (int i = 0; i < 4; i++) acc[mt][nt][i] = 0.f;

    u32 xorw = (u32)(g * 16);   // B-read swizzle term (o&7 == g)

    #pragma unroll 1
    for (int tap = 0; tap < 9; tap++) {
        int dy = tap / 3, dx = tap - dy*3;
        int rb = wid*32 + dy*128 + dx + g;        // A row for m-frag base
        u32 xorv = (u32)(((dx + g) & 7) * 16);    // A-read swizzle term
        const unsigned char* Wt = sW + tap * WTILE;
        const unsigned char* A0 = sA + rb * 128;
        #pragma unroll
        for (int kt = 0; kt < 4; kt++) {
            u32 aoff = (u32)(kt*32 + 4*t4);
            u32 oA  = aoff ^ xorv;
            u32 oA2 = (aoff + 16) ^ xorv;
            u32 bo0 = aoff ^ xorw;
            u32 bo1 = (aoff + 16) ^ xorw;
            u32 bfr[4][2];
            #pragma unroll
            for (int nt = 0; nt < 4; nt++) {
                const unsigned char* wrow = Wt + (nt*8 + g)*128;
                bfr[nt][0] = *(const u32*)(wrow + bo0);
                bfr[nt][1] = *(const u32*)(wrow + bo1);
            }
            #pragma unroll
            for (int mt = 0; mt < 2; mt++) {
                const unsigned char* Am = A0 + mt*16*128;
                u32 a0 = *(const u32*)(Am + oA);
                u32 a1 = *(const u32*)(Am + 8*128 + oA);
                u32 a2 = *(const u32*)(Am + oA2);
                u32 a3 = *(const u32*)(Am + 8*128 + oA2);
                #pragma unroll
                for (int nt = 0; nt < 4; nt++)
                    mma16816(acc[mt][nt], a0, a1, a2, a3, bfr[nt][0], bfr[nt][1]);
            }
        }
    }

    // ---- epilogue: D frag c0=(m=g,n=2t4) c1=(g,2t4+1) c2=(g+8,2t4) c3=(g+8,2t4+1) ----
    #pragma unroll
    for (int mt = 0; mt < 2; mt++) {
        int pl = wid*32 + mt*16 + g;
        #pragma unroll
        for (int nt = 0; nt < 4; nt++) {
            int o = og*32 + nt*8 + 2*t4;
            size_t d = ((size_t)(b*OUTC + o))*HW + p0 + pl;
            out[d]          = acc[mt][nt][0];
            out[d + HW]     = acc[mt][nt][1];
            out[d + 8]      = acc[mt][nt][2];
            out[d + HW + 8] = acc[mt][nt][3];
        }
    }
}

// ---------------- Kernel 6: subtract wrapped edge contributions ----------------
__global__ void fixup_kernel(const float* __restrict__ x, float* __restrict__ out) {
    extern __shared__ float fs[];
    float* w6 = fs;                    // 64o*64c*6
    float* Rs = fs + 64*64*6;          // 64c*131
    float* Ls = Rs + 64*131;           // 64c*130
    int b = blockIdx.x, tid = threadIdx.x;
    const float* wsrc = g_weight + (size_t)b*WPB;
    for (int idx = tid; idx < 64*64*6; idx += 256) {
        int o = idx/(64*6), r = idx%(64*6), c = r/6, j = r%6;
        int dy = j >> 1, side = j & 1;
        w6[idx] = wsrc[(o*64 + c)*9 + dy*3 + (side ? 2 : 0)];
    }
    const float* xb = x + (size_t)b * C * HW;
    for (int idx = tid; idx < 64*131; idx += 256) {
        int c = idx/131, jj = idx%131;
        int q = jj - 1;                 // value = Xflat(q*128 - 1)
        float v = 0.f;
        if (q >= 1 && q <= 128) v = xb[(size_t)c*HW + q*128 - 1];
        Rs[idx] = v;
    }
    for (int idx = tid; idx < 64*130; idx += 256) {
        int c = idx/130, u = idx%130;   // value = Xflat(u*128)
        float v = 0.f;
        if (u <= 127) v = xb[(size_t)c*HW + u*128];
        Ls[idx] = v;
    }
    __syncthreads();
    for (int t = tid; t < 64*128; t += 256) {
        int o = t >> 7, y = t & 127;
        float a0 = 0.f, a1 = 0.f;
        for (int c = 0; c < 64; c++) {
            const float* wp = &w6[(o*64 + c)*6];
            const float* rp = &Rs[c*131 + y];
            const float* lp = &Ls[c*130 + y];
            a0 += wp[0]*rp[0] + wp[2]*rp[1] + wp[4]*rp[2];
            a1 += wp[1]*lp[0] + wp[3]*lp[1] + wp[5]*lp[2];
        }
        size_t base = ((size_t)(b*OUTC + o))*HW + (size_t)y*128;
        out[base]       -= a0;
        out[base + 127] -= a1;
    }
}

extern "C" void kernel_launch(void* const* d_in, const int* in_sizes, int n_in,
                              void* d_out, int out_size) {
    const float* x  = (const float*)d_in[0];
    const float* W1 = (const float*)d_in[1];
    const float* b1 = (const float*)d_in[2];
    const float* W2 = (const float*)d_in[3];
    const float* b2 = (const float*)d_in[4];
    float* out = (float*)d_out;

    float *stats, *hidden, *weight;
    __half *wh, *xh;
    cudaGetSymbolAddress((void**)&stats,  g_stats);
    cudaGetSymbolAddress((void**)&hidden, g_hidden);
    cudaGetSymbolAddress((void**)&weight, g_weight);
    cudaGetSymbolAddress((void**)&wh, g_wh);
    cudaGetSymbolAddress((void**)&xh, g_xh);

    cudaFuncSetAttribute(conv_kernel,  cudaFuncAttributeMaxDynamicSharedMemorySize, CONV_SMEM);
    cudaFuncSetAttribute(fixup_kernel, cudaFuncAttributeMaxDynamicSharedMemorySize, (64*64*6 + 64*131 + 64*130) * 4);

    stats_kernel<<<BB*C, 256>>>(x, stats);
    hidden_kernel<<<BB, HIDDEN>>>(stats, W1, b1, hidden);
    weight_kernel<<<WPB/128, 128>>>(hidden, W2, b2, weight, wh);
    dim3 tg(HW/128, BB);
    transpose_kernel<<<tg, 256>>>(x, xh);
    dim3 cg(64, 2, BB);
    conv_kernel<<<cg, 256, CONV_SMEM>>>(xh, wh, out);
    fixup_kernel<<<BB, 256, (64*64*6 + 64*131 + 64*130) * 4>>>(x, out);
}